// round 10
// baseline (speedup 1.0000x reference)
#include <cuda_runtime.h>

typedef unsigned long long ull;

#define NLAYER 4
#define TSEQ   34
#define VOCAB  14
#define BSEQ   16
#define TROWS  9
#define NTHR   (BSEQ * TROWS)       // 144 threads = 4.5 warps
#define KV_STRIDE 412               // floats per seq buffer
#define BUF   (BSEQ * KV_STRIDE)    // 6592 floats per kv buffer
#define DYN_FLOATS (2 * BUF)        // double-buffered kv
#define DYN_BYTES  (DYN_FLOATS * 4) // 52736 B
#define OFF_IDX BUF                 // idx ints live in buf1 during prologue only
#define LW 112
#define OFF_LNF_W 448
#define OFF_LNF_B 454
#define OFF_HEAD  460               // 84 floats (7 vocab-pairs x 6)
#define OFF_TOK   544
#define OFF_POS   586
#define W_TOTAL   688

__device__ __forceinline__ ull pk(float lo, float hi) {
    ull r; asm("mov.b64 %0,{%1,%2};" : "=l"(r) : "f"(lo), "f"(hi)); return r;
}
__device__ __forceinline__ void upk(ull v, float& lo, float& hi) {
    asm("mov.b64 {%0,%1},%2;" : "=f"(lo), "=f"(hi) : "l"(v));
}
__device__ __forceinline__ ull ffma2(ull a, ull b, ull c) {
    ull d; asm("fma.rn.f32x2 %0,%1,%2,%3;" : "=l"(d) : "l"(a), "l"(b), "l"(c)); return d;
}
__device__ __forceinline__ ull fmul2(ull a, ull b) {
    ull d; asm("mul.rn.f32x2 %0,%1,%2;" : "=l"(d) : "l"(a), "l"(b)); return d;
}
__device__ __forceinline__ ull fadd2(ull a, ull b) {
    ull d; asm("add.rn.f32x2 %0,%1,%2;" : "=l"(d) : "l"(a), "l"(b)); return d;
}
__device__ __forceinline__ float ex2f(float x) {
    float r; asm("ex2.approx.f32 %0,%1;" : "=f"(r) : "f"(x)); return r;
}
__device__ __forceinline__ float rcpf(float x) {
    float r; asm("rcp.approx.f32 %0,%1;" : "=f"(r) : "f"(x)); return r;
}
__device__ __forceinline__ ull exp2pair(ull s) {
    float a, b; upk(s, a, b); return pk(ex2f(a), ex2f(b));
}
__device__ __forceinline__ ull dot2(const ull* q, const ull* k) {
    return ffma2(q[0], k[0], ffma2(q[1], k[1], fmul2(q[2], k[2])));
}

__device__ __forceinline__ void lnorm(const float* x, const float* w, const float* b, float* h) {
    float m = (x[0] + x[1] + x[2] + x[3] + x[4] + x[5]) * (1.f / 6.f);
    float var = 0.f;
    #pragma unroll
    for (int d = 0; d < 6; d++) { float c = x[d] - m; var += c * c; h[d] = c; }
    float inv = rsqrtf(var * (1.f / 6.f) + 1e-5f);
    #pragma unroll
    for (int d = 0; d < 6; d++) h[d] = h[d] * inv * w[d] + b[d];
}

// layernorm + q/k/v projections for one token (pair-packed heads)
__device__ __forceinline__ void qkv6(const float* x, const float* Wl,
                                     ull* q, ull* k, ull* v) {
    float h[6];
    lnorm(x, Wl + 90, Wl + 96, h);
    ull hp[3] = { pk(h[0], h[3]), pk(h[1], h[4]), pk(h[2], h[5]) };
    const ull* WQ = (const ull*)(Wl);
    const ull* WK = (const ull*)(Wl + 18);
    const ull* WV = (const ull*)(Wl + 36);
    #pragma unroll
    for (int d = 0; d < 3; d++) {
        ull aq = 0, ak = 0, av = 0;
        #pragma unroll
        for (int e = 0; e < 3; e++) {
            aq = ffma2(WQ[d * 3 + e], hp[e], aq);
            ak = ffma2(WK[d * 3 + e], hp[e], ak);
            av = ffma2(WV[d * 3 + e], hp[e], av);
        }
        q[d] = aq; k[d] = ak; v[d] = av;
    }
}

// softmax-normalize + output projection + residual for one token
__device__ __forceinline__ void proj_res(const ull* WO, ull sum,
                                         ull A0, ull A1, ull A2, float* x) {
    float s1, s2; upk(sum, s1, s2);
    ull rr = pk(rcpf(s1), rcpf(s2));
    ull t0 = fmul2(A0, rr), t1 = fmul2(A1, rr), t2 = fmul2(A2, rr);
    float c[6];
    upk(t0, c[0], c[3]); upk(t1, c[1], c[4]); upk(t2, c[2], c[5]);
    #pragma unroll
    for (int dp = 0; dp < 3; dp++) {
        ull acc = pk(x[2 * dp], x[2 * dp + 1]);
        #pragma unroll
        for (int i = 0; i < 6; i++) acc = ffma2(WO[dp * 6 + i], pk(c[i], c[i]), acc);
        upk(acc, x[2 * dp], x[2 * dp + 1]);
    }
}

// final layernorm + lm head, scatter store (14 floats = 7 ull)
__device__ __forceinline__ void head_out(const float* x, const float* W, float* outp) {
    float hf[6];
    lnorm(x, W + OFF_LNF_W, W + OFF_LNF_B, hf);
    ull hd[6];
    #pragma unroll
    for (int d = 0; d < 6; d++) hd[d] = pk(hf[d], hf[d]);
    const ull* WH = (const ull*)(W + OFF_HEAD);
    ull* o = (ull*)outp;
    #pragma unroll
    for (int vp = 0; vp < 7; vp++) {
        ull r = 0;
        #pragma unroll
        for (int d = 0; d < 6; d++) r = ffma2(WH[vp * 6 + d], hd[d], r);
        o[vp] = r;
    }
}

__global__ void __launch_bounds__(NTHR, 5)
addtx_kernel(const int* __restrict__ idx,
             const float* __restrict__ tok_emb, const float* __restrict__ pos_enc,
             const float* __restrict__ ln_w,   const float* __restrict__ ln_b,
             const float* __restrict__ q1w,    const float* __restrict__ k1w,
             const float* __restrict__ v1w,    const float* __restrict__ q2w,
             const float* __restrict__ k2w,    const float* __restrict__ v2w,
             const float* __restrict__ out_w,  const float* __restrict__ lnf_w,
             const float* __restrict__ lnf_b,  const float* __restrict__ head_w,
             float* __restrict__ out)
{
    __shared__ __align__(16) float W[W_TOTAL];
    extern __shared__ __align__(16) float U[];   // kv buf0 | kv buf1 (idx during prologue)

    const int s   = threadIdx.x;        // seq in block 0..15
    const int r   = threadIdx.y;        // row 0..8; row 8 = half warp
    const int tid = r * BSEQ + s;
    const int b   = blockIdx.x * BSEQ + s;
    const bool full = (r < 8);
    const int t0  = full ? (2 + 4 * r) : 0;   // first owned token
    const int ntok = full ? 4 : 2;

    int* idxs = (int*)(U + OFF_IDX);

    // ---- coalesced idx staging (544 ints = 272 int2) ----
    for (int i = tid; i < BSEQ * TSEQ / 2; i += NTHR) {
        ((int2*)idxs)[i] = ((const int2*)(idx + (size_t)blockIdx.x * BSEQ * TSEQ))[i];
    }

    // ---- stage weights as (head1, head2) pairs ----
    const float SCL = 0.83298066476f;   // (1/sqrt(3)) * log2(e), folded into q weights
    for (int i = tid; i < NLAYER * 9; i += NTHR) {
        int l = i / 9, rr = i - l * 9;
        float* Wl = W + l * LW;
        Wl[     2 * rr    ] = q1w[i] * SCL;
        Wl[     2 * rr + 1] = q2w[i] * SCL;
        Wl[18 + 2 * rr    ] = k1w[i];
        Wl[18 + 2 * rr + 1] = k2w[i];
        Wl[36 + 2 * rr    ] = v1w[i];
        Wl[36 + 2 * rr + 1] = v2w[i];
    }
    for (int i = tid; i < NLAYER * 18; i += NTHR) {
        int l = i / 18, p2 = i - l * 18, dp = p2 / 6, col = p2 - dp * 6;
        W[l * LW + 54 + 2 * p2    ] = out_w[l * 36 + (2 * dp    ) * 6 + col];
        W[l * LW + 54 + 2 * p2 + 1] = out_w[l * 36 + (2 * dp + 1) * 6 + col];
    }
    for (int i = tid; i < NLAYER * 6; i += NTHR) {
        int l = i / 6, rr = i - l * 6;
        W[l * LW + 90 + rr] = ln_w[i];
        W[l * LW + 96 + rr] = ln_b[i];
    }
    if (tid < 6) { W[OFF_LNF_W + tid] = lnf_w[tid]; W[OFF_LNF_B + tid] = lnf_b[tid]; }
    for (int i = tid; i < 42; i += NTHR) {
        int vp = i / 6, d = i - vp * 6;
        W[OFF_HEAD + 2 * i    ] = head_w[(2 * vp    ) * 6 + d];
        W[OFF_HEAD + 2 * i + 1] = head_w[(2 * vp + 1) * 6 + d];
    }
    for (int i = tid; i < VOCAB * 3; i += NTHR) W[OFF_TOK + i] = tok_emb[i];
    for (int i = tid; i < TSEQ * 3; i += NTHR)  W[OFF_POS + i] = pos_enc[i];
    __syncthreads();

    // ---- embeddings for owned tokens ----
    float x[4][6];
    #pragma unroll
    for (int i = 0; i < 4; i++) {
        if (i < ntok) {
            int t = t0 + i;
            int tok = idxs[s * TSEQ + t];
            #pragma unroll
            for (int d = 0; d < 3; d++) {
                x[i][d]     = W[OFF_TOK + tok * 3 + d];
                x[i][d + 3] = W[OFF_POS + t * 3 + d];
            }
        }
    }

    #pragma unroll
    for (int l = 0; l < NLAYER; l++) {
        const float* Wl = W + l * LW;
        const ull* WO = (const ull*)(Wl + 54);
        float* buf = U + (l & 1) * BUF;                    // double buffer
        ulonglong2* kvw = (ulonglong2*)(buf + s * KV_STRIDE);
        const ulonglong2* kvr = kvw;

        ull qs[4][3];
        ull rk[2][3], rv[2][3];   // row-8 register k/v (self/cross path)

        // ---- phase A: qkv + publish ----
        if (full) {
            #pragma unroll
            for (int i = 0; i < 4; i++) {
                ull k[3], v[3];
                qkv6(x[i], Wl, qs[i], k, v);
                int t = t0 + i;
                kvw[t * 3 + 0] = make_ulonglong2(k[0], k[1]);
                kvw[t * 3 + 1] = make_ulonglong2(k[2], v[0]);
                kvw[t * 3 + 2] = make_ulonglong2(v[1], v[2]);
            }
        } else {
            #pragma unroll
            for (int i = 0; i < 2; i++) {
                qkv6(x[i], Wl, qs[i], rk[i], rv[i]);
                int t = i;   // tokens 0,1
                kvw[t * 3 + 0] = make_ulonglong2(rk[i][0], rk[i][1]);
                kvw[t * 3 + 1] = make_ulonglong2(rk[i][2], rv[i][0]);
                kvw[t * 3 + 2] = make_ulonglong2(rv[i][1], rv[i][2]);
            }
        }
        __syncthreads();   // single barrier per layer (double-buffered kv)

        // ---- phase B: attention ----
        ull sum[4], a0[4], a1[4], a2[4];
        #pragma unroll
        for (int i = 0; i < 4; i++) { sum[i] = 0; a0[i] = 0; a1[i] = 0; a2[i] = 0; }

        if (full) {
            // shared causal loop: one kv load serves 4 query tokens
            #pragma unroll 2
            for (int j = 0; j < t0; j++) {
                ulonglong2 p0 = kvr[j * 3 + 0];
                ulonglong2 p1 = kvr[j * 3 + 1];
                ulonglong2 p2 = kvr[j * 3 + 2];
                #pragma unroll
                for (int i = 0; i < 4; i++) {
                    ull sc = ffma2(qs[i][0], p0.x, ffma2(qs[i][1], p0.y, fmul2(qs[i][2], p1.x)));
                    ull e  = exp2pair(sc);
                    sum[i] = fadd2(sum[i], e);
                    a0[i] = ffma2(e, p1.y, a0[i]);
                    a1[i] = ffma2(e, p2.x, a1[i]);
                    a2[i] = ffma2(e, p2.y, a2[i]);
                }
            }
            // tail: j = t0+m contributes to queries i >= m (static unroll)
            #pragma unroll
            for (int m = 0; m < 4; m++) {
                int j = t0 + m;
                ulonglong2 p0 = kvr[j * 3 + 0];
                ulonglong2 p1 = kvr[j * 3 + 1];
                ulonglong2 p2 = kvr[j * 3 + 2];
                #pragma unroll
                for (int i = 0; i < 4; i++) {
                    if (i >= m) {
                        ull sc = ffma2(qs[i][0], p0.x, ffma2(qs[i][1], p0.y, fmul2(qs[i][2], p1.x)));
                        ull e  = exp2pair(sc);
                        sum[i] = fadd2(sum[i], e);
                        a0[i] = ffma2(e, p1.y, a0[i]);
                        a1[i] = ffma2(e, p2.x, a1[i]);
                        a2[i] = ffma2(e, p2.y, a2[i]);
                    }
                }
            }
        } else {
            // tokens 0,1: pure register self/cross
            ull e00 = exp2pair(dot2(qs[0], rk[0]));
            sum[0] = e00;
            a0[0] = fmul2(e00, rv[0][0]); a1[0] = fmul2(e00, rv[0][1]); a2[0] = fmul2(e00, rv[0][2]);
            ull e10 = exp2pair(dot2(qs[1], rk[0]));
            ull e11 = exp2pair(dot2(qs[1], rk[1]));
            sum[1] = fadd2(e10, e11);
            a0[1] = ffma2(e10, rv[0][0], fmul2(e11, rv[1][0]));
            a1[1] = ffma2(e10, rv[0][1], fmul2(e11, rv[1][1]));
            a2[1] = ffma2(e10, rv[0][2], fmul2(e11, rv[1][2]));
        }

        // ---- phase C: normalize + project + residual ----
        #pragma unroll
        for (int i = 0; i < 4; i++) {
            if (i < ntok) proj_res(WO, sum[i], a0[i], a1[i], a2[i], x[i]);
        }
    }

    // ---- final LN + lm head ----
    #pragma unroll
    for (int i = 0; i < 4; i++) {
        if (i < ntok) {
            int t = t0 + i;
            head_out(x[i], W, out + (size_t)(b * TSEQ + t) * VOCAB);
        }
    }
}

extern "C" void kernel_launch(void* const* d_in, const int* in_sizes, int n_in,
                              void* d_out, int out_size)
{
    const int*   idx     = (const int*)d_in[0];
    const float* tok_emb = (const float*)d_in[1];
    const float* pos_enc = (const float*)d_in[2];
    const float* ln_w    = (const float*)d_in[3];
    const float* ln_b    = (const float*)d_in[4];
    const float* q1w     = (const float*)d_in[5];
    const float* k1w     = (const float*)d_in[6];
    const float* v1w     = (const float*)d_in[7];
    const float* q2w     = (const float*)d_in[8];
    const float* k2w     = (const float*)d_in[9];
    const float* v2w     = (const float*)d_in[10];
    const float* out_w   = (const float*)d_in[11];
    const float* lnf_w   = (const float*)d_in[12];
    const float* lnf_b   = (const float*)d_in[13];
    const float* head_w  = (const float*)d_in[14];
    float* out = (float*)d_out;

    cudaFuncSetAttribute(addtx_kernel,
                         cudaFuncAttributeMaxDynamicSharedMemorySize, DYN_BYTES);

    const int batch = in_sizes[0] / TSEQ;      // 16384
    dim3 block(BSEQ, TROWS);
    dim3 grid(batch / BSEQ);                   // 1024
    addtx_kernel<<<grid, block, DYN_BYTES>>>(idx, tok_emb, pos_enc, ln_w, ln_b,
                                             q1w, k1w, v1w, q2w, k2w, v2w,
                                             out_w, lnf_w, lnf_b, head_w, out);
}

// round 13
// speedup vs baseline: 1.5939x; 1.5939x over previous
#include <cuda_runtime.h>

typedef unsigned long long ull;

#define NLAYER 4
#define TSEQ   34
#define VOCAB  14
#define BSEQ   16
#define TROWS  12
#define NTHR   (BSEQ * TROWS)       // 192 threads = 6 full warps
#define KV_STRIDE 412               // floats per seq buffer
#define BUF   (BSEQ * KV_STRIDE)    // 6592 floats per kv buffer
#define DYN_FLOATS (2 * BUF)        // double-buffered kv
#define DYN_BYTES  (DYN_FLOATS * 4) // 52736 B
#define OFF_IDX BUF                 // idx ints live in buf1 during prologue only
#define LW 112
#define OFF_LNF_W 448
#define OFF_LNF_B 454
#define OFF_HEAD  460               // 84 floats (7 vocab-pairs x 6)
#define OFF_TOK   544
#define OFF_POS   586
#define W_TOTAL   688

__device__ __forceinline__ ull pk(float lo, float hi) {
    ull r; asm("mov.b64 %0,{%1,%2};" : "=l"(r) : "f"(lo), "f"(hi)); return r;
}
__device__ __forceinline__ void upk(ull v, float& lo, float& hi) {
    asm("mov.b64 {%0,%1},%2;" : "=f"(lo), "=f"(hi) : "l"(v));
}
__device__ __forceinline__ ull ffma2(ull a, ull b, ull c) {
    ull d; asm("fma.rn.f32x2 %0,%1,%2,%3;" : "=l"(d) : "l"(a), "l"(b), "l"(c)); return d;
}
__device__ __forceinline__ ull fmul2(ull a, ull b) {
    ull d; asm("mul.rn.f32x2 %0,%1,%2;" : "=l"(d) : "l"(a), "l"(b)); return d;
}
__device__ __forceinline__ ull fadd2(ull a, ull b) {
    ull d; asm("add.rn.f32x2 %0,%1,%2;" : "=l"(d) : "l"(a), "l"(b)); return d;
}
__device__ __forceinline__ float ex2f(float x) {
    float r; asm("ex2.approx.f32 %0,%1;" : "=f"(r) : "f"(x)); return r;
}
__device__ __forceinline__ float rcpf(float x) {
    float r; asm("rcp.approx.f32 %0,%1;" : "=f"(r) : "f"(x)); return r;
}
__device__ __forceinline__ ull exp2pair(ull s) {
    float a, b; upk(s, a, b); return pk(ex2f(a), ex2f(b));
}
__device__ __forceinline__ ull dot2(const ull* q, const ull* k) {
    return ffma2(q[0], k[0], ffma2(q[1], k[1], fmul2(q[2], k[2])));
}

__device__ __forceinline__ void lnorm(const float* x, const float* w, const float* b, float* h) {
    float m = (x[0] + x[1] + x[2] + x[3] + x[4] + x[5]) * (1.f / 6.f);
    float var = 0.f;
    #pragma unroll
    for (int d = 0; d < 6; d++) { float c = x[d] - m; var += c * c; h[d] = c; }
    float inv = rsqrtf(var * (1.f / 6.f) + 1e-5f);
    #pragma unroll
    for (int d = 0; d < 6; d++) h[d] = h[d] * inv * w[d] + b[d];
}

// layernorm + q/k/v projections for one token (pair-packed heads)
__device__ __forceinline__ void qkv6(const float* x, const float* Wl,
                                     ull* q, ull* k, ull* v) {
    float h[6];
    lnorm(x, Wl + 90, Wl + 96, h);
    ull hp[3] = { pk(h[0], h[3]), pk(h[1], h[4]), pk(h[2], h[5]) };
    const ull* WQ = (const ull*)(Wl);
    const ull* WK = (const ull*)(Wl + 18);
    const ull* WV = (const ull*)(Wl + 36);
    #pragma unroll
    for (int d = 0; d < 3; d++) {
        ull aq = 0, ak = 0, av = 0;
        #pragma unroll
        for (int e = 0; e < 3; e++) {
            aq = ffma2(WQ[d * 3 + e], hp[e], aq);
            ak = ffma2(WK[d * 3 + e], hp[e], ak);
            av = ffma2(WV[d * 3 + e], hp[e], av);
        }
        q[d] = aq; k[d] = ak; v[d] = av;
    }
}

// softmax-normalize + output projection + residual for one token
__device__ __forceinline__ void proj_res(const ull* WO, ull sum,
                                         ull A0, ull A1, ull A2, float* x) {
    float s1, s2; upk(sum, s1, s2);
    ull rr = pk(rcpf(s1), rcpf(s2));
    ull t0 = fmul2(A0, rr), t1 = fmul2(A1, rr), t2 = fmul2(A2, rr);
    float c[6];
    upk(t0, c[0], c[3]); upk(t1, c[1], c[4]); upk(t2, c[2], c[5]);
    #pragma unroll
    for (int dp = 0; dp < 3; dp++) {
        ull acc = pk(x[2 * dp], x[2 * dp + 1]);
        #pragma unroll
        for (int i = 0; i < 6; i++) acc = ffma2(WO[dp * 6 + i], pk(c[i], c[i]), acc);
        upk(acc, x[2 * dp], x[2 * dp + 1]);
    }
}

// final layernorm + lm head, scatter store (14 floats = 7 ull)
__device__ __forceinline__ void head_out(const float* x, const float* W, float* outp) {
    float hf[6];
    lnorm(x, W + OFF_LNF_W, W + OFF_LNF_B, hf);
    ull hd[6];
    #pragma unroll
    for (int d = 0; d < 6; d++) hd[d] = pk(hf[d], hf[d]);
    const ull* WH = (const ull*)(W + OFF_HEAD);
    ull* o = (ull*)outp;
    #pragma unroll
    for (int vp = 0; vp < 7; vp++) {
        ull r = 0;
        #pragma unroll
        for (int d = 0; d < 6; d++) r = ffma2(WH[vp * 6 + d], hd[d], r);
        o[vp] = r;
    }
}

__global__ void __launch_bounds__(NTHR, 4)
addtx_kernel(const int* __restrict__ idx,
             const float* __restrict__ tok_emb, const float* __restrict__ pos_enc,
             const float* __restrict__ ln_w,   const float* __restrict__ ln_b,
             const float* __restrict__ q1w,    const float* __restrict__ k1w,
             const float* __restrict__ v1w,    const float* __restrict__ q2w,
             const float* __restrict__ k2w,    const float* __restrict__ v2w,
             const float* __restrict__ out_w,  const float* __restrict__ lnf_w,
             const float* __restrict__ lnf_b,  const float* __restrict__ head_w,
             float* __restrict__ out)
{
    __shared__ __align__(16) float W[W_TOTAL];
    extern __shared__ __align__(16) float U[];   // kv buf0 | kv buf1 (idx during prologue)

    const int s   = threadIdx.x;        // seq in block 0..15
    const int r   = threadIdx.y;        // row 0..11
    const int tid = r * BSEQ + s;
    const int b   = blockIdx.x * BSEQ + s;
    const bool full = (r < 11);
    const int t0  = full ? (3 * r + 1) : 0;   // first owned token (row11: token 0)
    const int ntok = full ? 3 : 1;

    int* idxs = (int*)(U + OFF_IDX);

    // ---- coalesced idx staging (544 ints = 272 int2) ----
    for (int i = tid; i < BSEQ * TSEQ / 2; i += NTHR) {
        ((int2*)idxs)[i] = ((const int2*)(idx + (size_t)blockIdx.x * BSEQ * TSEQ))[i];
    }

    // ---- stage weights as (head1, head2) pairs ----
    const float SCL = 0.83298066476f;   // (1/sqrt(3)) * log2(e), folded into q weights
    for (int i = tid; i < NLAYER * 9; i += NTHR) {
        int l = i / 9, rr = i - l * 9;
        float* Wl = W + l * LW;
        Wl[     2 * rr    ] = q1w[i] * SCL;
        Wl[     2 * rr + 1] = q2w[i] * SCL;
        Wl[18 + 2 * rr    ] = k1w[i];
        Wl[18 + 2 * rr + 1] = k2w[i];
        Wl[36 + 2 * rr    ] = v1w[i];
        Wl[36 + 2 * rr + 1] = v2w[i];
    }
    for (int i = tid; i < NLAYER * 18; i += NTHR) {
        int l = i / 18, p2 = i - l * 18, dp = p2 / 6, col = p2 - dp * 6;
        W[l * LW + 54 + 2 * p2    ] = out_w[l * 36 + (2 * dp    ) * 6 + col];
        W[l * LW + 54 + 2 * p2 + 1] = out_w[l * 36 + (2 * dp + 1) * 6 + col];
    }
    for (int i = tid; i < NLAYER * 6; i += NTHR) {
        int l = i / 6, rr = i - l * 6;
        W[l * LW + 90 + rr] = ln_w[i];
        W[l * LW + 96 + rr] = ln_b[i];
    }
    if (tid < 6) { W[OFF_LNF_W + tid] = lnf_w[tid]; W[OFF_LNF_B + tid] = lnf_b[tid]; }
    for (int i = tid; i < 42; i += NTHR) {
        int vp = i / 6, d = i - vp * 6;
        W[OFF_HEAD + 2 * i    ] = head_w[(2 * vp    ) * 6 + d];
        W[OFF_HEAD + 2 * i + 1] = head_w[(2 * vp + 1) * 6 + d];
    }
    for (int i = tid; i < VOCAB * 3; i += NTHR) W[OFF_TOK + i] = tok_emb[i];
    for (int i = tid; i < TSEQ * 3; i += NTHR)  W[OFF_POS + i] = pos_enc[i];
    __syncthreads();

    // ---- embeddings for owned tokens ----
    float x[3][6];
    #pragma unroll
    for (int i = 0; i < 3; i++) {
        if (i < ntok) {
            int t = t0 + i;
            int tok = idxs[s * TSEQ + t];
            #pragma unroll
            for (int d = 0; d < 3; d++) {
                x[i][d]     = W[OFF_TOK + tok * 3 + d];
                x[i][d + 3] = W[OFF_POS + t * 3 + d];
            }
        }
    }

    #pragma unroll
    for (int l = 0; l < NLAYER; l++) {
        const float* Wl = W + l * LW;
        const ull* WO = (const ull*)(Wl + 54);
        float* buf = U + (l & 1) * BUF;                    // double buffer
        ulonglong2* kvw = (ulonglong2*)(buf + s * KV_STRIDE);
        const ulonglong2* kvr = kvw;

        ull qs[3][3];
        ull rk[3], rv[3];   // row-11 register k/v (self path)

        // ---- phase A: qkv + publish ----
        if (full) {
            #pragma unroll
            for (int i = 0; i < 3; i++) {
                ull k[3], v[3];
                qkv6(x[i], Wl, qs[i], k, v);
                int t = t0 + i;
                kvw[t * 3 + 0] = make_ulonglong2(k[0], k[1]);
                kvw[t * 3 + 1] = make_ulonglong2(k[2], v[0]);
                kvw[t * 3 + 2] = make_ulonglong2(v[1], v[2]);
            }
        } else {
            qkv6(x[0], Wl, qs[0], rk, rv);
            kvw[0] = make_ulonglong2(rk[0], rk[1]);
            kvw[1] = make_ulonglong2(rk[2], rv[0]);
            kvw[2] = make_ulonglong2(rv[1], rv[2]);
        }
        __syncthreads();   // single barrier per layer (double-buffered kv)

        // ---- phase B: attention ----
        ull sum[3], a0[3], a1[3], a2[3];
        #pragma unroll
        for (int i = 0; i < 3; i++) { sum[i] = 0; a0[i] = 0; a1[i] = 0; a2[i] = 0; }

        if (full) {
            // shared causal loop: one kv load serves 3 query tokens
            #pragma unroll 2
            for (int j = 0; j < t0; j++) {
                ulonglong2 p0 = kvr[j * 3 + 0];
                ulonglong2 p1 = kvr[j * 3 + 1];
                ulonglong2 p2 = kvr[j * 3 + 2];
                #pragma unroll
                for (int i = 0; i < 3; i++) {
                    ull sc = ffma2(qs[i][0], p0.x, ffma2(qs[i][1], p0.y, fmul2(qs[i][2], p1.x)));
                    ull e  = exp2pair(sc);
                    sum[i] = fadd2(sum[i], e);
                    a0[i] = ffma2(e, p1.y, a0[i]);
                    a1[i] = ffma2(e, p2.x, a1[i]);
                    a2[i] = ffma2(e, p2.y, a2[i]);
                }
            }
            // tail: j = t0+m contributes to queries i >= m (static unroll)
            #pragma unroll
            for (int m = 0; m < 3; m++) {
                int j = t0 + m;
                ulonglong2 p0 = kvr[j * 3 + 0];
                ulonglong2 p1 = kvr[j * 3 + 1];
                ulonglong2 p2 = kvr[j * 3 + 2];
                #pragma unroll
                for (int i = 0; i < 3; i++) {
                    if (i >= m) {
                        ull sc = ffma2(qs[i][0], p0.x, ffma2(qs[i][1], p0.y, fmul2(qs[i][2], p1.x)));
                        ull e  = exp2pair(sc);
                        sum[i] = fadd2(sum[i], e);
                        a0[i] = ffma2(e, p1.y, a0[i]);
                        a1[i] = ffma2(e, p2.x, a1[i]);
                        a2[i] = ffma2(e, p2.y, a2[i]);
                    }
                }
            }
        } else {
            // token 0: pure register self term
            ull e00 = exp2pair(dot2(qs[0], rk));
            sum[0] = e00;
            a0[0] = fmul2(e00, rv[0]); a1[0] = fmul2(e00, rv[1]); a2[0] = fmul2(e00, rv[2]);
        }

        // ---- phase C: normalize + project + residual ----
        #pragma unroll
        for (int i = 0; i < 3; i++) {
            if (i < ntok) proj_res(WO, sum[i], a0[i], a1[i], a2[i], x[i]);
        }
    }

    // ---- final LN + lm head ----
    #pragma unroll
    for (int i = 0; i < 3; i++) {
        if (i < ntok) {
            int t = t0 + i;
            head_out(x[i], W, out + (size_t)(b * TSEQ + t) * VOCAB);
        }
    }
}

extern "C" void kernel_launch(void* const* d_in, const int* in_sizes, int n_in,
                              void* d_out, int out_size)
{
    const int*   idx     = (const int*)d_in[0];
    const float* tok_emb = (const float*)d_in[1];
    const float* pos_enc = (const float*)d_in[2];
    const float* ln_w    = (const float*)d_in[3];
    const float* ln_b    = (const float*)d_in[4];
    const float* q1w     = (const float*)d_in[5];
    const float* k1w     = (const float*)d_in[6];
    const float* v1w     = (const float*)d_in[7];
    const float* q2w     = (const float*)d_in[8];
    const float* k2w     = (const float*)d_in[9];
    const float* v2w     = (const float*)d_in[10];
    const float* out_w   = (const float*)d_in[11];
    const float* lnf_w   = (const float*)d_in[12];
    const float* lnf_b   = (const float*)d_in[13];
    const float* head_w  = (const float*)d_in[14];
    float* out = (float*)d_out;

    cudaFuncSetAttribute(addtx_kernel,
                         cudaFuncAttributeMaxDynamicSharedMemorySize, DYN_BYTES);

    const int batch = in_sizes[0] / TSEQ;      // 16384
    dim3 block(BSEQ, TROWS);
    dim3 grid(batch / BSEQ);                   // 1024
    addtx_kernel<<<grid, block, DYN_BYTES>>>(idx, tok_emb, pos_enc, ln_w, ln_b,
                                             q1w, k1w, v1w, q2w, k2w, v2w,
                                             out_w, lnf_w, lnf_b, head_w, out);
}

// round 14
// speedup vs baseline: 1.9113x; 1.1991x over previous
#include <cuda_runtime.h>

typedef unsigned long long ull;

#define NLAYER 4
#define TSEQ   34
#define VOCAB  14
#define BSEQ   16
#define TROWS  17
#define NTHR   (BSEQ * TROWS)     // 272
#define KV_STRIDE 412             // floats per seq (34*12=408 used, padded for banks)
#define BUF    (BSEQ * KV_STRIDE) // 6592 floats per kv buffer
#define DYN_FLOATS (2 * BUF)
#define DYN_BYTES  (DYN_FLOATS * 4)   // 52736 B
#define OFF_IDX BUF               // idx ints live in buf1 during prologue only
#define LW 112
#define OFF_LNF_W 448
#define OFF_LNF_B 454
#define OFF_HEAD  460             // 84 floats (7 vocab-pairs x 6)
#define OFF_TOK   544             // 42
#define OFF_POS   586             // 102
#define W_TOTAL   688

__device__ __forceinline__ ull pk(float lo, float hi) {
    ull r; asm("mov.b64 %0,{%1,%2};" : "=l"(r) : "f"(lo), "f"(hi)); return r;
}
__device__ __forceinline__ void upk(ull v, float& lo, float& hi) {
    asm("mov.b64 {%0,%1},%2;" : "=f"(lo), "=f"(hi) : "l"(v));
}
__device__ __forceinline__ ull ffma2(ull a, ull b, ull c) {
    ull d; asm("fma.rn.f32x2 %0,%1,%2,%3;" : "=l"(d) : "l"(a), "l"(b), "l"(c)); return d;
}
__device__ __forceinline__ ull fmul2(ull a, ull b) {
    ull d; asm("mul.rn.f32x2 %0,%1,%2;" : "=l"(d) : "l"(a), "l"(b)); return d;
}
__device__ __forceinline__ ull fadd2(ull a, ull b) {
    ull d; asm("add.rn.f32x2 %0,%1,%2;" : "=l"(d) : "l"(a), "l"(b)); return d;
}
__device__ __forceinline__ float ex2f(float x) {
    float r; asm("ex2.approx.f32 %0,%1;" : "=f"(r) : "f"(x)); return r;
}
__device__ __forceinline__ float rcpf(float x) {
    float r; asm("rcp.approx.f32 %0,%1;" : "=f"(r) : "f"(x)); return r;
}
__device__ __forceinline__ ull exp2pair(ull s) {
    float a, b; upk(s, a, b); return pk(ex2f(a), ex2f(b));
}
__device__ __forceinline__ ull dot2(const ull* q, const ull* k) {
    return ffma2(q[0], k[0], ffma2(q[1], k[1], fmul2(q[2], k[2])));
}

__device__ __forceinline__ void lnorm(const float* x, const float* w, const float* b, float* h) {
    float m = (x[0] + x[1] + x[2] + x[3] + x[4] + x[5]) * (1.f / 6.f);
    float var = 0.f;
    #pragma unroll
    for (int d = 0; d < 6; d++) { float c = x[d] - m; var += c * c; h[d] = c; }
    float inv = rsqrtf(var * (1.f / 6.f) + 1e-5f);
    #pragma unroll
    for (int d = 0; d < 6; d++) h[d] = h[d] * inv * w[d] + b[d];
}

__global__ void __launch_bounds__(NTHR, 4)
addtx_kernel(const int* __restrict__ idx,
             const float* __restrict__ tok_emb, const float* __restrict__ pos_enc,
             const float* __restrict__ ln_w,   const float* __restrict__ ln_b,
             const float* __restrict__ q1w,    const float* __restrict__ k1w,
             const float* __restrict__ v1w,    const float* __restrict__ q2w,
             const float* __restrict__ k2w,    const float* __restrict__ v2w,
             const float* __restrict__ out_w,  const float* __restrict__ lnf_w,
             const float* __restrict__ lnf_b,  const float* __restrict__ head_w,
             float* __restrict__ out)
{
    __shared__ __align__(16) float W[W_TOTAL];
    extern __shared__ __align__(16) float U[];  // kv buf0 | kv buf1 (idx during prologue)

    const int s   = threadIdx.x;        // seq in block 0..15
    const int ty  = threadIdx.y;        // token-pair row 0..16
    const int tid = ty * BSEQ + s;
    const int b   = blockIdx.x * BSEQ + s;
    const int ta  = 2 * ty, tb = 2 * ty + 1;

    // ---- coalesced idx staging (544 ints = 272 int2, one per thread) ----
    ((int2*)(U + OFF_IDX))[tid] = ((const int2*)(idx + (size_t)blockIdx.x * BSEQ * TSEQ))[tid];

    // ---- stage weights as (head1, head2) pairs ----
    const float SCL = 0.83298066476f;   // (1/sqrt(3)) * log2(e), folded into q weights
    for (int i = tid; i < NLAYER * 9; i += NTHR) {
        int l = i / 9, r = i - l * 9;
        float* Wl = W + l * LW;
        Wl[     2 * r    ] = q1w[i] * SCL;
        Wl[     2 * r + 1] = q2w[i] * SCL;
        Wl[18 + 2 * r    ] = k1w[i];
        Wl[18 + 2 * r + 1] = k2w[i];
        Wl[36 + 2 * r    ] = v1w[i];
        Wl[36 + 2 * r + 1] = v2w[i];
    }
    for (int i = tid; i < NLAYER * 18; i += NTHR) {
        int l = i / 18, p2 = i - l * 18, dp = p2 / 6, col = p2 - dp * 6;
        W[l * LW + 54 + 2 * p2    ] = out_w[l * 36 + (2 * dp    ) * 6 + col];
        W[l * LW + 54 + 2 * p2 + 1] = out_w[l * 36 + (2 * dp + 1) * 6 + col];
    }
    for (int i = tid; i < NLAYER * 6; i += NTHR) {
        int l = i / 6, r = i - l * 6;
        W[l * LW + 90 + r] = ln_w[i];
        W[l * LW + 96 + r] = ln_b[i];
    }
    if (tid < 6) { W[OFF_LNF_W + tid] = lnf_w[tid]; W[OFF_LNF_B + tid] = lnf_b[tid]; }
    for (int i = tid; i < 42; i += NTHR) {          // 7 vocab-pairs x 6 dims
        int vp = i / 6, d = i - vp * 6;
        W[OFF_HEAD + 2 * i    ] = head_w[(2 * vp    ) * 6 + d];
        W[OFF_HEAD + 2 * i + 1] = head_w[(2 * vp + 1) * 6 + d];
    }
    for (int i = tid; i < VOCAB * 3; i += NTHR) W[OFF_TOK + i] = tok_emb[i];
    for (int i = tid; i < TSEQ * 3; i += NTHR)  W[OFF_POS + i] = pos_enc[i];
    __syncthreads();

    // ---- embeddings for both owned tokens (idx from smem) ----
    const int tok_a = ((const int*)(U + OFF_IDX))[s * TSEQ + ta];
    const int tok_b = ((const int*)(U + OFF_IDX))[s * TSEQ + tb];
    float xa[6], xb[6];
    #pragma unroll
    for (int d = 0; d < 3; d++) {
        xa[d]     = W[OFF_TOK + tok_a * 3 + d];
        xa[d + 3] = W[OFF_POS + ta * 3 + d];
        xb[d]     = W[OFF_TOK + tok_b * 3 + d];
        xb[d + 3] = W[OFF_POS + tb * 3 + d];
    }

    #pragma unroll
    for (int l = 0; l < NLAYER; l++) {
        const float* Wl = W + l * LW;
        const ull* WQ = (const ull*)(Wl);
        const ull* WK = (const ull*)(Wl + 18);
        const ull* WV = (const ull*)(Wl + 36);
        const ull* WO = (const ull*)(Wl + 54);
        // double-buffered kv: layer l uses buffer (l & 1) -> one barrier per layer
        float* buf = U + (l & 1) * BUF;
        ulonglong2* kvw = (ulonglong2*)(buf + s * KV_STRIDE);
        const ulonglong2* kvr = kvw;

        float ha[6], hb[6];
        lnorm(xa, Wl + 90, Wl + 96, ha);
        lnorm(xb, Wl + 90, Wl + 96, hb);

        ull hpa[3] = { pk(ha[0], ha[3]), pk(ha[1], ha[4]), pk(ha[2], ha[5]) };
        ull hpb[3] = { pk(hb[0], hb[3]), pk(hb[1], hb[4]), pk(hb[2], hb[5]) };

        ull qa[3], ka[3], va[3], qb[3], kb[3], vb[3];
        #pragma unroll
        for (int d = 0; d < 3; d++) {
            ull aq = 0, ak = 0, av = 0, bq = 0, bk = 0, bv = 0;
            #pragma unroll
            for (int e = 0; e < 3; e++) {
                ull wq = WQ[d * 3 + e], wk = WK[d * 3 + e], wv = WV[d * 3 + e];
                aq = ffma2(wq, hpa[e], aq);  bq = ffma2(wq, hpb[e], bq);
                ak = ffma2(wk, hpa[e], ak);  bk = ffma2(wk, hpb[e], bk);
                av = ffma2(wv, hpa[e], av);  bv = ffma2(wv, hpb[e], bv);
            }
            qa[d] = aq; ka[d] = ak; va[d] = av;
            qb[d] = bq; kb[d] = bk; vb[d] = bv;
        }

        // publish k/v (pair-interleaved): {k0,k1},{k2,v0},{v1,v2}
        kvw[ta * 3 + 0] = make_ulonglong2(ka[0], ka[1]);
        kvw[ta * 3 + 1] = make_ulonglong2(ka[2], va[0]);
        kvw[ta * 3 + 2] = make_ulonglong2(va[1], va[2]);
        kvw[tb * 3 + 0] = make_ulonglong2(kb[0], kb[1]);
        kvw[tb * 3 + 1] = make_ulonglong2(kb[2], vb[0]);
        kvw[tb * 3 + 2] = make_ulonglong2(vb[1], vb[2]);
        __syncthreads();   // single barrier per layer (publish -> read)

        // self / cross terms straight from registers (j = ta for a; j = ta, tb for b)
        ull eaa = exp2pair(dot2(qa, ka));
        ull suma = eaa;
        ull aac0 = fmul2(eaa, va[0]), aac1 = fmul2(eaa, va[1]), aac2 = fmul2(eaa, va[2]);

        ull eba = exp2pair(dot2(qb, ka));
        ull ebb = exp2pair(dot2(qb, kb));
        ull sumb = fadd2(eba, ebb);
        ull bac0 = ffma2(eba, va[0], fmul2(ebb, vb[0]));
        ull bac1 = ffma2(eba, va[1], fmul2(ebb, vb[1]));
        ull bac2 = ffma2(eba, va[2], fmul2(ebb, vb[2]));

        // shared causal loop: one kv load serves both query tokens
        #pragma unroll 2
        for (int j = 0; j < ta; j++) {
            ulonglong2 p0 = kvr[j * 3 + 0];
            ulonglong2 p1 = kvr[j * 3 + 1];
            ulonglong2 p2 = kvr[j * 3 + 2];
            ull sa = ffma2(qa[0], p0.x, ffma2(qa[1], p0.y, fmul2(qa[2], p1.x)));
            ull sb = ffma2(qb[0], p0.x, ffma2(qb[1], p0.y, fmul2(qb[2], p1.x)));
            ull ea = exp2pair(sa);
            ull eb = exp2pair(sb);
            suma = fadd2(suma, ea);       sumb = fadd2(sumb, eb);
            aac0 = ffma2(ea, p1.y, aac0); bac0 = ffma2(eb, p1.y, bac0);
            aac1 = ffma2(ea, p2.x, aac1); bac1 = ffma2(eb, p2.x, bac1);
            aac2 = ffma2(ea, p2.y, aac2); bac2 = ffma2(eb, p2.y, bac2);
        }

        // normalize + output projection + residual
        float sa1, sa2, sb1, sb2;
        upk(suma, sa1, sa2); upk(sumb, sb1, sb2);
        ull ra = pk(rcpf(sa1), rcpf(sa2));
        ull rb = pk(rcpf(sb1), rcpf(sb2));
        float cA[6], cB[6];
        { ull t0 = fmul2(aac0, ra), t1 = fmul2(aac1, ra), t2 = fmul2(aac2, ra);
          upk(t0, cA[0], cA[3]); upk(t1, cA[1], cA[4]); upk(t2, cA[2], cA[5]); }
        { ull t0 = fmul2(bac0, rb), t1 = fmul2(bac1, rb), t2 = fmul2(bac2, rb);
          upk(t0, cB[0], cB[3]); upk(t1, cB[1], cB[4]); upk(t2, cB[2], cB[5]); }
        ull cdA[6], cdB[6];
        #pragma unroll
        for (int i = 0; i < 6; i++) { cdA[i] = pk(cA[i], cA[i]); cdB[i] = pk(cB[i], cB[i]); }
        #pragma unroll
        for (int dp = 0; dp < 3; dp++) {
            ull accA = pk(xa[2 * dp], xa[2 * dp + 1]);
            ull accB = pk(xb[2 * dp], xb[2 * dp + 1]);
            #pragma unroll
            for (int i = 0; i < 6; i++) {
                ull wo = WO[dp * 6 + i];
                accA = ffma2(wo, cdA[i], accA);
                accB = ffma2(wo, cdB[i], accB);
            }
            upk(accA, xa[2 * dp], xa[2 * dp + 1]);
            upk(accB, xb[2 * dp], xb[2 * dp + 1]);
        }
    }

    // ---- final LN + lm head (vocab-pair FFMA2), direct 8B stores ----
    float hfa[6], hfb[6];
    lnorm(xa, W + OFF_LNF_W, W + OFF_LNF_B, hfa);
    lnorm(xb, W + OFF_LNF_W, W + OFF_LNF_B, hfb);
    ull hda[6], hdb[6];
    #pragma unroll
    for (int d = 0; d < 6; d++) { hda[d] = pk(hfa[d], hfa[d]); hdb[d] = pk(hfb[d], hfb[d]); }

    const ull* WH = (const ull*)(W + OFF_HEAD);
    ull* oa = (ull*)(out + (size_t)(b * TSEQ + ta) * VOCAB);
    ull* ob = (ull*)(out + (size_t)(b * TSEQ + tb) * VOCAB);
    #pragma unroll
    for (int vp = 0; vp < 7; vp++) {
        ull rA = 0, rB = 0;
        #pragma unroll
        for (int d = 0; d < 6; d++) {
            ull wh = WH[vp * 6 + d];
            rA = ffma2(wh, hda[d], rA);
            rB = ffma2(wh, hdb[d], rB);
        }
        oa[vp] = rA;
        ob[vp] = rB;
    }
}

extern "C" void kernel_launch(void* const* d_in, const int* in_sizes, int n_in,
                              void* d_out, int out_size)
{
    const int*   idx     = (const int*)d_in[0];
    const float* tok_emb = (const float*)d_in[1];
    const float* pos_enc = (const float*)d_in[2];
    const float* ln_w    = (const float*)d_in[3];
    const float* ln_b    = (const float*)d_in[4];
    const float* q1w     = (const float*)d_in[5];
    const float* k1w     = (const float*)d_in[6];
    const float* v1w     = (const float*)d_in[7];
    const float* q2w     = (const float*)d_in[8];
    const float* k2w     = (const float*)d_in[9];
    const float* v2w     = (const float*)d_in[10];
    const float* out_w   = (const float*)d_in[11];
    const float* lnf_w   = (const float*)d_in[12];
    const float* lnf_b   = (const float*)d_in[13];
    const float* head_w  = (const float*)d_in[14];
    float* out = (float*)d_out;

    cudaFuncSetAttribute(addtx_kernel,
                         cudaFuncAttributeMaxDynamicSharedMemorySize, DYN_BYTES);

    const int batch = in_sizes[0] / TSEQ;      // 16384
    dim3 block(BSEQ, TROWS);
    dim3 grid(batch / BSEQ);                   // 1024
    addtx_kernel<<<grid, block, DYN_BYTES>>>(idx, tok_emb, pos_enc, ln_w, ln_b,
                                             q1w, k1w, v1w, q2w, k2w, v2w,
                                             out_w, lnf_w, lnf_b, head_w, out);
}

// round 15
// speedup vs baseline: 2.3110x; 1.2091x over previous
#include <cuda_runtime.h>

typedef unsigned long long ull;

#define NLAYER 4
#define TSEQ   34
#define VOCAB  14
#define BSEQ   16
#define TROWS  17
#define NTHR   (BSEQ * TROWS)     // 272
#define KV_STRIDE 412             // floats per seq (34*12=408 used, padded for banks)
#define BUF    (BSEQ * KV_STRIDE) // 6592 floats per kv buffer
#define DYN_FLOATS (2 * BUF)
#define DYN_BYTES  (DYN_FLOATS * 4)   // 52736 B
#define OFF_IDX BUF               // idx ints live in buf1 during prologue only
#define LW 112
#define OFF_LNF_W 448
#define OFF_LNF_B 454
#define OFF_HEAD  460             // 84 floats (7 vocab-pairs x 6)
#define OFF_TOK   544             // 42
#define OFF_POS   586             // 102
#define W_TOTAL   688

__device__ __forceinline__ ull pk(float lo, float hi) {
    ull r; asm("mov.b64 %0,{%1,%2};" : "=l"(r) : "f"(lo), "f"(hi)); return r;
}
__device__ __forceinline__ void upk(ull v, float& lo, float& hi) {
    asm("mov.b64 {%0,%1},%2;" : "=f"(lo), "=f"(hi) : "l"(v));
}
__device__ __forceinline__ ull ffma2(ull a, ull b, ull c) {
    ull d; asm("fma.rn.f32x2 %0,%1,%2,%3;" : "=l"(d) : "l"(a), "l"(b), "l"(c)); return d;
}
__device__ __forceinline__ ull fmul2(ull a, ull b) {
    ull d; asm("mul.rn.f32x2 %0,%1,%2;" : "=l"(d) : "l"(a), "l"(b)); return d;
}
__device__ __forceinline__ ull fadd2(ull a, ull b) {
    ull d; asm("add.rn.f32x2 %0,%1,%2;" : "=l"(d) : "l"(a), "l"(b)); return d;
}
__device__ __forceinline__ float ex2f(float x) {
    float r; asm("ex2.approx.f32 %0,%1;" : "=f"(r) : "f"(x)); return r;
}
__device__ __forceinline__ float rcpf(float x) {
    float r; asm("rcp.approx.f32 %0,%1;" : "=f"(r) : "f"(x)); return r;
}
__device__ __forceinline__ ull exp2pair(ull s) {
    float a, b; upk(s, a, b); return pk(ex2f(a), ex2f(b));
}
__device__ __forceinline__ ull dot2(const ull* q, const ull* k) {
    return ffma2(q[0], k[0], ffma2(q[1], k[1], fmul2(q[2], k[2])));
}

__device__ __forceinline__ void lnorm(const float* x, const float* w, const float* b, float* h) {
    float m = (x[0] + x[1] + x[2] + x[3] + x[4] + x[5]) * (1.f / 6.f);
    float var = 0.f;
    #pragma unroll
    for (int d = 0; d < 6; d++) { float c = x[d] - m; var += c * c; h[d] = c; }
    float inv = rsqrtf(var * (1.f / 6.f) + 1e-5f);
    #pragma unroll
    for (int d = 0; d < 6; d++) h[d] = h[d] * inv * w[d] + b[d];
}

__global__ void __launch_bounds__(NTHR, 3)
addtx_kernel(const int* __restrict__ idx,
             const float* __restrict__ tok_emb, const float* __restrict__ pos_enc,
             const float* __restrict__ ln_w,   const float* __restrict__ ln_b,
             const float* __restrict__ q1w,    const float* __restrict__ k1w,
             const float* __restrict__ v1w,    const float* __restrict__ q2w,
             const float* __restrict__ k2w,    const float* __restrict__ v2w,
             const float* __restrict__ out_w,  const float* __restrict__ lnf_w,
             const float* __restrict__ lnf_b,  const float* __restrict__ head_w,
             float* __restrict__ out)
{
    __shared__ __align__(16) float W[W_TOTAL];
    extern __shared__ __align__(16) float U[];  // kv buf0 | kv buf1 (idx during prologue)

    const int s   = threadIdx.x;        // seq in block 0..15
    const int ty  = threadIdx.y;        // row 0..16; warp w = rows {2w, 2w+1}; row 16 = half warp
    const int tid = ty * BSEQ + s;
    const int b   = blockIdx.x * BSEQ + s;
    // straggler remap: half-warp row 16 gets pair 0 (shortest, zero loop trips);
    // full warps get pairs 1..16 (warp w: pairs 2w+1, 2w+2 -> adjacent lengths)
    const int pr  = (ty == 16) ? 0 : (ty + 1);
    const int ta  = 2 * pr, tb = ta + 1;

    // ---- coalesced idx staging (544 ints = 272 int2, one per thread) ----
    ((int2*)(U + OFF_IDX))[tid] = ((const int2*)(idx + (size_t)blockIdx.x * BSEQ * TSEQ))[tid];

    // ---- stage weights as (head1, head2) pairs ----
    const float SCL = 0.83298066476f;   // (1/sqrt(3)) * log2(e), folded into q weights
    for (int i = tid; i < NLAYER * 9; i += NTHR) {
        int l = i / 9, r = i - l * 9;
        float* Wl = W + l * LW;
        Wl[     2 * r    ] = q1w[i] * SCL;
        Wl[     2 * r + 1] = q2w[i] * SCL;
        Wl[18 + 2 * r    ] = k1w[i];
        Wl[18 + 2 * r + 1] = k2w[i];
        Wl[36 + 2 * r    ] = v1w[i];
        Wl[36 + 2 * r + 1] = v2w[i];
    }
    for (int i = tid; i < NLAYER * 18; i += NTHR) {
        int l = i / 18, p2 = i - l * 18, dp = p2 / 6, col = p2 - dp * 6;
        W[l * LW + 54 + 2 * p2    ] = out_w[l * 36 + (2 * dp    ) * 6 + col];
        W[l * LW + 54 + 2 * p2 + 1] = out_w[l * 36 + (2 * dp + 1) * 6 + col];
    }
    for (int i = tid; i < NLAYER * 6; i += NTHR) {
        int l = i / 6, r = i - l * 6;
        W[l * LW + 90 + r] = ln_w[i];
        W[l * LW + 96 + r] = ln_b[i];
    }
    if (tid < 6) { W[OFF_LNF_W + tid] = lnf_w[tid]; W[OFF_LNF_B + tid] = lnf_b[tid]; }
    for (int i = tid; i < 42; i += NTHR) {          // 7 vocab-pairs x 6 dims
        int vp = i / 6, d = i - vp * 6;
        W[OFF_HEAD + 2 * i    ] = head_w[(2 * vp    ) * 6 + d];
        W[OFF_HEAD + 2 * i + 1] = head_w[(2 * vp + 1) * 6 + d];
    }
    for (int i = tid; i < VOCAB * 3; i += NTHR) W[OFF_TOK + i] = tok_emb[i];
    for (int i = tid; i < TSEQ * 3; i += NTHR)  W[OFF_POS + i] = pos_enc[i];
    __syncthreads();

    // ---- embeddings for both owned tokens (idx from smem) ----
    const int tok_a = ((const int*)(U + OFF_IDX))[s * TSEQ + ta];
    const int tok_b = ((const int*)(U + OFF_IDX))[s * TSEQ + tb];
    float xa[6], xb[6];
    #pragma unroll
    for (int d = 0; d < 3; d++) {
        xa[d]     = W[OFF_TOK + tok_a * 3 + d];
        xa[d + 3] = W[OFF_POS + ta * 3 + d];
        xb[d]     = W[OFF_TOK + tok_b * 3 + d];
        xb[d + 3] = W[OFF_POS + tb * 3 + d];
    }

    #pragma unroll
    for (int l = 0; l < NLAYER; l++) {
        const float* Wl = W + l * LW;
        const ull* WQ = (const ull*)(Wl);
        const ull* WK = (const ull*)(Wl + 18);
        const ull* WV = (const ull*)(Wl + 36);
        const ull* WO = (const ull*)(Wl + 54);
        // double-buffered kv: layer l uses buffer (l & 1) -> one barrier per layer
        float* buf = U + (l & 1) * BUF;
        ulonglong2* kvw = (ulonglong2*)(buf + s * KV_STRIDE);
        const ulonglong2* kvr = kvw;

        float ha[6], hb[6];
        lnorm(xa, Wl + 90, Wl + 96, ha);
        lnorm(xb, Wl + 90, Wl + 96, hb);

        ull hpa[3] = { pk(ha[0], ha[3]), pk(ha[1], ha[4]), pk(ha[2], ha[5]) };
        ull hpb[3] = { pk(hb[0], hb[3]), pk(hb[1], hb[4]), pk(hb[2], hb[5]) };

        ull qa[3], ka[3], va[3], qb[3], kb[3], vb[3];
        #pragma unroll
        for (int d = 0; d < 3; d++) {
            ull aq = 0, ak = 0, av = 0, bq = 0, bk = 0, bv = 0;
            #pragma unroll
            for (int e = 0; e < 3; e++) {
                ull wq = WQ[d * 3 + e], wk = WK[d * 3 + e], wv = WV[d * 3 + e];
                aq = ffma2(wq, hpa[e], aq);  bq = ffma2(wq, hpb[e], bq);
                ak = ffma2(wk, hpa[e], ak);  bk = ffma2(wk, hpb[e], bk);
                av = ffma2(wv, hpa[e], av);  bv = ffma2(wv, hpb[e], bv);
            }
            qa[d] = aq; ka[d] = ak; va[d] = av;
            qb[d] = bq; kb[d] = bk; vb[d] = bv;
        }

        // publish k/v (pair-interleaved): {k0,k1},{k2,v0},{v1,v2}
        kvw[ta * 3 + 0] = make_ulonglong2(ka[0], ka[1]);
        kvw[ta * 3 + 1] = make_ulonglong2(ka[2], va[0]);
        kvw[ta * 3 + 2] = make_ulonglong2(va[1], va[2]);
        kvw[tb * 3 + 0] = make_ulonglong2(kb[0], kb[1]);
        kvw[tb * 3 + 1] = make_ulonglong2(kb[2], vb[0]);
        kvw[tb * 3 + 2] = make_ulonglong2(vb[1], vb[2]);
        __syncthreads();   // single barrier per layer (publish -> read)

        // self / cross terms straight from registers (j = ta for a; j = ta, tb for b)
        ull eaa = exp2pair(dot2(qa, ka));
        ull suma = eaa;
        ull aac0 = fmul2(eaa, va[0]), aac1 = fmul2(eaa, va[1]), aac2 = fmul2(eaa, va[2]);

        ull eba = exp2pair(dot2(qb, ka));
        ull ebb = exp2pair(dot2(qb, kb));
        ull sumb = fadd2(eba, ebb);
        ull bac0 = ffma2(eba, va[0], fmul2(ebb, vb[0]));
        ull bac1 = ffma2(eba, va[1], fmul2(ebb, vb[1]));
        ull bac2 = ffma2(eba, va[2], fmul2(ebb, vb[2]));

        // shared causal loop: one kv load serves both query tokens,
        // running pointer + 1-iteration prefetch
        const ulonglong2* kp = kvr;
        ulonglong2 n0 = kp[0], n1 = kp[1], n2 = kp[2];
        #pragma unroll 2
        for (int j = 0; j < ta; j++) {
            ulonglong2 p0 = n0, p1 = n1, p2 = n2;
            kp += 3;
            n0 = kp[0];
            n1 = kp[1];
            n2 = kp[2];
            ull sa = ffma2(qa[0], p0.x, ffma2(qa[1], p0.y, fmul2(qa[2], p1.x)));
            ull sb = ffma2(qb[0], p0.x, ffma2(qb[1], p0.y, fmul2(qb[2], p1.x)));
            ull ea = exp2pair(sa);
            ull eb = exp2pair(sb);
            suma = fadd2(suma, ea);       sumb = fadd2(sumb, eb);
            aac0 = ffma2(ea, p1.y, aac0); bac0 = ffma2(eb, p1.y, bac0);
            aac1 = ffma2(ea, p2.x, aac1); bac1 = ffma2(eb, p2.x, bac1);
            aac2 = ffma2(ea, p2.y, aac2); bac2 = ffma2(eb, p2.y, bac2);
        }

        // normalize + output projection + residual
        float sa1, sa2, sb1, sb2;
        upk(suma, sa1, sa2); upk(sumb, sb1, sb2);
        ull ra = pk(rcpf(sa1), rcpf(sa2));
        ull rb = pk(rcpf(sb1), rcpf(sb2));
        float cA[6], cB[6];
        { ull t0 = fmul2(aac0, ra), t1 = fmul2(aac1, ra), t2 = fmul2(aac2, ra);
          upk(t0, cA[0], cA[3]); upk(t1, cA[1], cA[4]); upk(t2, cA[2], cA[5]); }
        { ull t0 = fmul2(bac0, rb), t1 = fmul2(bac1, rb), t2 = fmul2(bac2, rb);
          upk(t0, cB[0], cB[3]); upk(t1, cB[1], cB[4]); upk(t2, cB[2], cB[5]); }
        ull cdA[6], cdB[6];
        #pragma unroll
        for (int i = 0; i < 6; i++) { cdA[i] = pk(cA[i], cA[i]); cdB[i] = pk(cB[i], cB[i]); }
        #pragma unroll
        for (int dp = 0; dp < 3; dp++) {
            ull accA = pk(xa[2 * dp], xa[2 * dp + 1]);
            ull accB = pk(xb[2 * dp], xb[2 * dp + 1]);
            #pragma unroll
            for (int i = 0; i < 6; i++) {
                ull wo = WO[dp * 6 + i];
                accA = ffma2(wo, cdA[i], accA);
                accB = ffma2(wo, cdB[i], accB);
            }
            upk(accA, xa[2 * dp], xa[2 * dp + 1]);
            upk(accB, xb[2 * dp], xb[2 * dp + 1]);
        }
    }

    // ---- final LN + lm head (vocab-pair FFMA2), direct 8B stores ----
    float hfa[6], hfb[6];
    lnorm(xa, W + OFF_LNF_W, W + OFF_LNF_B, hfa);
    lnorm(xb, W + OFF_LNF_W, W + OFF_LNF_B, hfb);
    ull hda[6], hdb[6];
    #pragma unroll
    for (int d = 0; d < 6; d++) { hda[d] = pk(hfa[d], hfa[d]); hdb[d] = pk(hfb[d], hfb[d]); }

    const ull* WH = (const ull*)(W + OFF_HEAD);
    ull* oa = (ull*)(out + (size_t)(b * TSEQ + ta) * VOCAB);
    ull* ob = (ull*)(out + (size_t)(b * TSEQ + tb) * VOCAB);
    #pragma unroll
    for (int vp = 0; vp < 7; vp++) {
        ull rA = 0, rB = 0;
        #pragma unroll
        for (int d = 0; d < 6; d++) {
            ull wh = WH[vp * 6 + d];
            rA = ffma2(wh, hda[d], rA);
            rB = ffma2(wh, hdb[d], rB);
        }
        oa[vp] = rA;
        ob[vp] = rB;
    }
}

extern "C" void kernel_launch(void* const* d_in, const int* in_sizes, int n_in,
                              void* d_out, int out_size)
{
    const int*   idx     = (const int*)d_in[0];
    const float* tok_emb = (const float*)d_in[1];
    const float* pos_enc = (const float*)d_in[2];
    const float* ln_w    = (const float*)d_in[3];
    const float* ln_b    = (const float*)d_in[4];
    const float* q1w     = (const float*)d_in[5];
    const float* k1w     = (const float*)d_in[6];
    const float* v1w     = (const float*)d_in[7];
    const float* q2w     = (const float*)d_in[8];
    const float* k2w     = (const float*)d_in[9];
    const float* v2w     = (const float*)d_in[10];
    const float* out_w   = (const float*)d_in[11];
    const float* lnf_w   = (const float*)d_in[12];
    const float* lnf_b   = (const float*)d_in[13];
    const float* head_w  = (const float*)d_in[14];
    float* out = (float*)d_out;

    cudaFuncSetAttribute(addtx_kernel,
                         cudaFuncAttributeMaxDynamicSharedMemorySize, DYN_BYTES);

    const int batch = in_sizes[0] / TSEQ;      // 16384
    dim3 block(BSEQ, TROWS);
    dim3 grid(batch / BSEQ);                   // 1024
    addtx_kernel<<<grid, block, DYN_BYTES>>>(idx, tok_emb, pos_enc, ln_w, ln_b,
                                             q1w, k1w, v1w, q2w, k2w, v2w,
                                             out_w, lnf_w, lnf_b, head_w, out);
}